// round 16
// baseline (speedup 1.0000x reference)
#include <cuda_runtime.h>
#include <cuda_fp16.h>
#include <cstdint>

#define NEG_INF -1e30f
typedef __half fp16;

// ---------------- scratch ----------------
__device__ __align__(256) fp16  g_xh[2048*512], g_xl[2048*512];
__device__ __align__(256) fp16  g_yh[2048*512], g_yl[2048*512];
__device__ __align__(256) fp16  g_Wqph[512*4608], g_Wqpl[512*4608];  // [Wq | Wp]
__device__ __align__(256) fp16  g_Wkh[512*4096];
__device__ __align__(256) fp16  g_Wvh[512*4096];
__device__ __align__(256) fp16  g_Qh[16*1024*512], g_Ql[16*1024*512];   // [h][2048][512]
__device__ __align__(256) fp16  g_KTh[16*512*1024];                     // [hb][d][t]
__device__ __align__(256) fp16  g_V1T[16*512*1024];                     // [hb][d][s]
__device__ __align__(256) fp16  g_AF[(size_t)16*1024*1024];             // [hb][s][t] P=exp(e-m_blk)
__device__ __align__(256) float2 g_St[16*1024*8];                       // per (row, 128-col block): (m, s)
__device__ __align__(256) float g_XP[2048*512];
__device__ int g_mask[1024];

// ---------------- helpers ----------------
__device__ __forceinline__ uint32_t smem_u32(const void* p) {
    uint32_t a;
    asm("{ .reg .u64 t; cvta.to.shared.u64 t, %1; cvt.u32.u64 %0, t; }" : "=r"(a) : "l"(p));
    return a;
}
#define SWZA(x) ((x) ^ (((x) >> 3) & 0x70))
#define SWZB(x) ((x) ^ (((x) >> 4) & 0x70))
__device__ __forceinline__ void cp16(uint32_t dst, const void* src) {
    asm volatile("cp.async.cg.shared.global [%0], [%1], 16;" :: "r"(dst), "l"(src));
}
#define CP_COMMIT() asm volatile("cp.async.commit_group;" ::: "memory")
#define CP_WAIT1()  asm volatile("cp.async.wait_group 1;" ::: "memory")
__device__ __forceinline__ void ldm4(uint32_t* d, uint32_t a) {
    asm volatile("ldmatrix.sync.aligned.m8n8.x4.shared.b16 {%0,%1,%2,%3}, [%4];"
                 : "=r"(d[0]), "=r"(d[1]), "=r"(d[2]), "=r"(d[3]) : "r"(a));
}
__device__ __forceinline__ void ldm4t(uint32_t* d, uint32_t a) {
    asm volatile("ldmatrix.sync.aligned.m8n8.x4.trans.shared.b16 {%0,%1,%2,%3}, [%4];"
                 : "=r"(d[0]), "=r"(d[1]), "=r"(d[2]), "=r"(d[3]) : "r"(a));
}
__device__ __forceinline__ void mma16816(float* c, const uint32_t* a, uint32_t b0, uint32_t b1) {
    asm volatile("mma.sync.aligned.m16n8k16.row.col.f32.f16.f16.f32 "
                 "{%0,%1,%2,%3}, {%4,%5,%6,%7}, {%8,%9}, {%0,%1,%2,%3};"
                 : "+f"(c[0]), "+f"(c[1]), "+f"(c[2]), "+f"(c[3])
                 : "r"(a[0]), "r"(a[1]), "r"(a[2]), "r"(a[3]), "r"(b0), "r"(b1));
}
__device__ __forceinline__ void split2(float v, fp16& h, fp16& l) {
    h = __float2half(v);
    l = __float2half(v - __half2float(h));
}
__device__ __forceinline__ void split4_store(const float4 v, fp16* Hb, fp16* Lb, size_t off) {
    fp16 h0,l0,h1,l1,h2,l2,h3,l3;
    split2(v.x,h0,l0); split2(v.y,h1,l1); split2(v.z,h2,l2); split2(v.w,h3,l3);
    __half2* H = reinterpret_cast<__half2*>(Hb + off);
    __half2* L = reinterpret_cast<__half2*>(Lb + off);
    H[0] = __halves2half2(h0,h1); H[1] = __halves2half2(h2,h3);
    L[0] = __halves2half2(l0,l1); L[1] = __halves2half2(l2,l3);
}
__device__ __forceinline__ const fp16* pick(const fp16* p0, const fp16* p1, const fp16* p2, int s) {
    return s == 0 ? p0 : (s == 1 ? p1 : p2);
}

// ---------------- segmented GEMM core: CTA 128x128, 8 warps of 64x32, 3 stages ----
#define STG 32768
#define SMTOT (3*STG)

__device__ __forceinline__ void gemm_core(
    const fp16* A0, const fp16* A1, const fp16* A2,
    const fp16* B0, const fp16* B1, const fp16* B2,
    int KT, int ksh, int Kseg, int ldb, int m0, int n0,
    uint32_t sb, int tid, float c[4][4][4])
{
    const int wid = tid >> 5, lane = tid & 31;
    const int wm = (wid & 1) * 64, wn = (wid >> 1) * 32;

    uint32_t saoff[4], sboff[4];
#pragma unroll
    for (int i = 0; i < 4; i++) {
        int idx = tid + i * 256;
        saoff[i] = SWZA((idx >> 3) * 128 + (idx & 7) * 16);
        sboff[i] = 16384 + SWZB((idx >> 4) * 256 + (idx & 15) * 16);
    }
    const int aRow = tid >> 3, aCol = (tid & 7) * 8;
    const int bRow = tid >> 4, bCol = (tid & 15) * 8;
    const size_t aStep = (size_t)32 * Kseg;
    const size_t bStep = (size_t)16 * ldb;
    const size_t bAdv  = (size_t)64 * ldb;
    const int msk = (1 << ksh) - 1;

    const fp16* pA = A0;
    const fp16* pB = B0;
    int load_kt = 0;
    auto ldst = [&](int st) {
        if ((load_kt & msk) == 0) {
            int seg = load_kt >> ksh;
            pA = pick(A0, A1, A2, seg) + (size_t)(m0 + aRow) * Kseg + aCol;
            pB = pick(B0, B1, B2, seg) + (size_t)bRow * ldb + n0 + bCol;
        }
        uint32_t sa = sb + st * STG;
#pragma unroll
        for (int i = 0; i < 4; i++) cp16(sa + saoff[i], pA + i * aStep);
#pragma unroll
        for (int i = 0; i < 4; i++) cp16(sa + sboff[i], pB + i * bStep);
        pA += 64; pB += bAdv;
        load_kt++;
    };

    ldst(0); CP_COMMIT();
    ldst(1); CP_COMMIT();

    const int lo16 = lane & 15, hi2 = lane >> 4;
    uint32_t abase[4], bbase[2];
#pragma unroll
    for (int im = 0; im < 4; im++) abase[im] = (wm + im * 16 + lo16) * 128 + hi2 * 16;
#pragma unroll
    for (int in2 = 0; in2 < 2; in2++) bbase[in2] = lo16 * 256 + (wn + in2 * 16 + hi2 * 8) * 2;

    auto body = [&](int st) {
        const uint32_t sa = sb + st * STG, sbb = sa + 16384;
        uint32_t af[2][4][4], bfr[2][2][4];
#pragma unroll
        for (int im = 0; im < 4; im++) ldm4(af[0][im], sa + SWZA(abase[im]));
#pragma unroll
        for (int in2 = 0; in2 < 2; in2++) ldm4t(bfr[0][in2], sbb + SWZB(bbase[in2]));
#pragma unroll
        for (int kk = 0; kk < 4; kk++) {
            const int cur = kk & 1, nxt = cur ^ 1;
            if (kk < 3) {
#pragma unroll
                for (int im = 0; im < 4; im++) ldm4(af[nxt][im], sa + SWZA(abase[im] + (kk + 1) * 32));
#pragma unroll
                for (int in2 = 0; in2 < 2; in2++) ldm4t(bfr[nxt][in2], sbb + SWZB(bbase[in2] + (kk + 1) * 4096));
            }
#pragma unroll
            for (int im = 0; im < 4; im++)
#pragma unroll
                for (int in2 = 0; in2 < 2; in2++) {
                    mma16816(c[im][in2 * 2],     af[cur][im], bfr[cur][in2][0], bfr[cur][in2][1]);
                    mma16816(c[im][in2 * 2 + 1], af[cur][im], bfr[cur][in2][2], bfr[cur][in2][3]);
                }
        }
    };

    int st = 0;
    for (int kt = 0; kt < KT - 2; kt++) {
        CP_WAIT1();
        __syncthreads();
        int st2 = st + 2; if (st2 >= 3) st2 -= 3;
        ldst(st2);
        CP_COMMIT();
        body(st);
        st++; if (st == 3) st = 0;
    }
#pragma unroll
    for (int t2 = 0; t2 < 2; t2++) {
        CP_WAIT1();
        __syncthreads();
        CP_COMMIT();
        body(st);
        st++; if (st == 3) st = 0;
    }
    __syncthreads();
}

__device__ __forceinline__ void stage_acc(float* stf, int tid, float c[4][4][4]) {
    const int wid = tid >> 5, lane = tid & 31;
    const int wm = (wid & 1) * 64, wn = (wid >> 1) * 32;
    const int rin = lane >> 2, cp2 = (lane & 3) * 2;
#pragma unroll
    for (int im = 0; im < 4; im++)
#pragma unroll
        for (int i8 = 0; i8 < 4; i8++) {
            int rr = wm + im * 16 + rin, cc = wn + i8 * 8 + cp2;
            stf[rr * 129 + cc]           = c[im][i8][0];
            stf[rr * 129 + cc + 1]       = c[im][i8][1];
            stf[(rr + 8) * 129 + cc]     = c[im][i8][2];
            stf[(rr + 8) * 129 + cc + 1] = c[im][i8][3];
        }
    __syncthreads();
}

// ---------------- mega projection: z=0 Q (2-pass) + xp (3-pass), z=1 K(T) 2-pass, z=2 V(T) 1-pass ----
__global__ void __launch_bounds__(256, 2)
gemm_proj(const float* __restrict__ bq, const float* __restrict__ bk,
          const float* __restrict__ bv)
{
    extern __shared__ char smem[];
    const int z = blockIdx.z;
    const int xt = (z == 0) ? 36 : 32;
    if ((int)blockIdx.x >= xt) return;
    const uint32_t sb = smem_u32(smem);
    const int tid = threadIdx.x;
    const int m0 = blockIdx.y * 128, n0 = blockIdx.x * 128;

    float c[4][4][4];
#pragma unroll
    for (int i = 0; i < 4; i++)
#pragma unroll
        for (int j = 0; j < 4; j++)
#pragma unroll
            for (int q = 0; q < 4; q++) c[i][j][q] = 0.f;

    if (z == 0) {
        if (n0 < 4096)
            gemm_core(g_xh, g_xl, nullptr, g_Wqph, g_Wqph, nullptr, 16, 3, 512, 4608, m0, n0, sb, tid, c);
        else
            gemm_core(g_xh, g_xh, g_xl, g_Wqph, g_Wqpl, g_Wqph, 24, 3, 512, 4608, m0, n0, sb, tid, c);
    } else if (z == 1)
        gemm_core(g_yh, g_yl, nullptr, g_Wkh, g_Wkh, nullptr, 16, 3, 512, 4096, m0, n0, sb, tid, c);
    else
        gemm_core(g_yh, nullptr, nullptr, g_Wvh, nullptr, nullptr, 8, 3, 512, 4096, m0, n0, sb, tid, c);

    float* stf = (float*)smem;
    stage_acc(stf, tid, c);

#pragma unroll 4
    for (int i = 0; i < 64; i++) {
        const int idx = tid + i * 256;
        int r, cc;
        if (z == 0) { r = idx >> 7; cc = idx & 127; } else { r = idx & 127; cc = idx >> 7; }
        float v = stf[r * 129 + cc];
        const int row2 = m0 + r, col = n0 + cc;
        if (z == 0) {
            if (col < 4096) {
                v += __ldg(bq + col);
                int h = col >> 9, d = col & 511;
                fp16 hi, lo; split2(v, hi, lo);
                size_t base = ((size_t)h * 2048 + row2) * 512 + d;
                g_Qh[base] = hi; g_Ql[base] = lo;
            } else {
                g_XP[(size_t)row2 * 512 + (col - 4096)] = v;
            }
        } else if (z == 1) {
            v += __ldg(bk + col);
            int h = col >> 9, d = col & 511;
            int b = row2 >> 10, t = row2 & 1023;
            g_KTh[(size_t)(h * 2 + b) * 512 * 1024 + (size_t)d * 1024 + t] = __float2half(v);
        } else {
            v += __ldg(bv + col);
            int h = col >> 9, d = col & 511;
            int b = row2 >> 10, s = row2 & 1023;
            g_V1T[(size_t)(h * 2 + b) * 512 * 1024 + (size_t)d * 1024 + s] = __float2half(v);
        }
    }
}

// ---------------- energy + fused block-softmax: writes P=exp(e-m_blk) fp16 + (m,s) stats ----
__global__ void __launch_bounds__(256, 2)
gemm_energy(void)
{
    extern __shared__ char smem[];
    const uint32_t sb = smem_u32(smem);
    const int tid = threadIdx.x, z = blockIdx.z;
    const int m0 = blockIdx.y * 128, n0 = blockIdx.x * 128;
    const fp16* Ah = g_Qh + (size_t)z * 1024 * 512;
    const fp16* Al = g_Ql + (size_t)z * 1024 * 512;
    const fp16* Bh = g_KTh + (size_t)z * 512 * 1024;

    float c[4][4][4];
#pragma unroll
    for (int i = 0; i < 4; i++)
#pragma unroll
        for (int j = 0; j < 4; j++)
#pragma unroll
            for (int q = 0; q < 4; q++) c[i][j][q] = 0.f;

    gemm_core(Ah, Al, nullptr, Bh, Bh, nullptr, 16, 3, 512, 1024, m0, n0, sb, tid, c);

    float* stf = (float*)smem;
    stage_acc(stf, tid, c);

    // fused block softmax: warp w handles rows [w*16, w*16+16)
    const int w = tid >> 5, lane = tid & 31;
    const int cb = lane * 4;
    int mk0 = g_mask[n0 + cb], mk1 = g_mask[n0 + cb + 1];
    int mk2 = g_mask[n0 + cb + 2], mk3 = g_mask[n0 + cb + 3];
    const size_t afrow0 = (size_t)z * 1048576 + (size_t)m0 * 1024 + n0;
    const int nb = n0 >> 7;
#pragma unroll 2
    for (int rr = w * 16; rr < w * 16 + 16; rr++) {
        const float* sr = stf + rr * 129 + cb;
        float e0 = mk0 ? sr[0] : NEG_INF;
        float e1 = mk1 ? sr[1] : NEG_INF;
        float e2 = mk2 ? sr[2] : NEG_INF;
        float e3 = mk3 ? sr[3] : NEG_INF;
        float m = fmaxf(fmaxf(e0, e1), fmaxf(e2, e3));
#pragma unroll
        for (int o = 16; o > 0; o >>= 1) m = fmaxf(m, __shfl_xor_sync(~0u, m, o));
        float p0 = mk0 ? __expf(e0 - m) : 0.f;
        float p1 = mk1 ? __expf(e1 - m) : 0.f;
        float p2 = mk2 ? __expf(e2 - m) : 0.f;
        float p3 = mk3 ? __expf(e3 - m) : 0.f;
        float s = p0 + p1 + p2 + p3;
#pragma unroll
        for (int o = 16; o > 0; o >>= 1) s += __shfl_xor_sync(~0u, s, o);
        __half2* q = reinterpret_cast<__half2*>(g_AF + afrow0 + (size_t)rr * 1024 + cb);
        q[0] = __floats2half2_rn(p0, p1);
        q[1] = __floats2half2_rn(p2, p3);
        if (lane == 0)
            g_St[((size_t)z * 1024 + m0 + rr) * 8 + nb] = make_float2(m, s);
    }
}

// ---------------- rowfix: per row, reduce 8 block stats and rescale AF in place ----------------
__global__ void __launch_bounds__(128)
rowfix_kernel(void)
{
    const int row = blockIdx.x;          // 0..16383 = z*1024 + s
    const int tid = threadIdx.x;
    __shared__ float fsh[8];
    __shared__ float2 st[8];
    if (tid < 8) st[tid] = g_St[(size_t)row * 8 + tid];
    __syncthreads();
    if (tid == 0) {
        float mr = st[0].x;
#pragma unroll
        for (int i = 1; i < 8; i++) mr = fmaxf(mr, st[i].x);
        float sr = 0.f;
        float ex[8];
#pragma unroll
        for (int i = 0; i < 8; i++) { ex[i] = __expf(st[i].x - mr); sr += st[i].y * ex[i]; }
        float inv = 1.0f / sr;
#pragma unroll
        for (int i = 0; i < 8; i++) fsh[i] = (st[i].y > 0.f) ? ex[i] * inv : 0.f;
    }
    __syncthreads();
    uint4* p = reinterpret_cast<uint4*>(g_AF + (size_t)row * 1024);
    uint4 v = p[tid];
    const float f = fsh[tid >> 4];
    __half2* h = reinterpret_cast<__half2*>(&v);
#pragma unroll
    for (int i = 0; i < 4; i++) {
        float2 t = __half22float2(h[i]);
        h[i] = __floats2half2_rn(t.x * f, t.y * f);
    }
    p[tid] = v;
}

// ---------------- out ----------------
__global__ void __launch_bounds__(256, 2)
gemm_out(const float* __restrict__ gamma, float* __restrict__ out)
{
    extern __shared__ char smem[];
    const uint32_t sb = smem_u32(smem);
    const int tid = threadIdx.x, z = blockIdx.z;
    const int m0 = blockIdx.y * 128, n0 = blockIdx.x * 128;
    const fp16* A0 = g_V1T + (size_t)z * 512 * 1024;
    const fp16* B0 = g_AF + (size_t)z * 1024 * 1024;

    float c[4][4][4];
#pragma unroll
    for (int i = 0; i < 4; i++)
#pragma unroll
        for (int j = 0; j < 4; j++)
#pragma unroll
            for (int q = 0; q < 4; q++) c[i][j][q] = 0.f;

    gemm_core(A0, nullptr, nullptr, B0, nullptr, nullptr, 16, 4, 1024, 1024, m0, n0, sb, tid, c);

    float* stf = (float*)smem;
    stage_acc(stf, tid, c);

    const int h = z >> 1, b = z & 1;
    const float g = __ldg(gamma + h);
    const float inv = 1.0f / (g + 1.0f);
#pragma unroll 4
    for (int i = 0; i < 64; i++) {
        const int idx = tid + i * 256;
        const int r = idx & 127, cc = idx >> 7;
        const int d = m0 + r, t = n0 + cc;
        float v = stf[r * 129 + cc];
        float xp = __ldg(g_XP + ((size_t)b * 1024 + t) * 512 + d);
        out[(((size_t)(b * 8 + h)) * 1024 + t) * 512 + d] = (g * v + xp) * inv;
    }
}

// ---------------- merged prep (incl. mask normalization at block 6400) ----------------
__global__ void prep_all(const float* __restrict__ x, const float* __restrict__ y,
                         const float* __restrict__ Wq, const float* __restrict__ Wp,
                         const float* __restrict__ Wk, const float* __restrict__ Wv,
                         const unsigned char* __restrict__ mask_raw)
{
    const int b = blockIdx.x, tid = threadIdx.x;
    if (b < 2048) {
        int i = b * 256 + tid;
        int sel = i >= 262144;
        size_t j4 = (size_t)(i & 262143) * 4;
        float4 v = *reinterpret_cast<const float4*>((sel ? y : x) + j4);
        if (sel) split4_store(v, g_yh, g_yl, j4);
        else     split4_store(v, g_xh, g_xl, j4);
    } else if (b < 4096) {
        int i = (b - 2048) * 256 + tid;
        int r = i >> 10;
        size_t c4 = (size_t)(i & 1023) * 4;
        float4 v = *reinterpret_cast<const float4*>(Wq + (size_t)r * 4096 + c4);
        split4_store(v, g_Wqph, g_Wqpl, (size_t)r * 4608 + c4);
    } else if (b < 4352) {
        int i = (b - 4096) * 256 + tid;
        int r = i >> 7;
        size_t c4 = (size_t)(i & 127) * 4;
        float4 v = *reinterpret_cast<const float4*>(Wp + (size_t)r * 512 + c4);
        split4_store(v, g_Wqph, g_Wqpl, (size_t)r * 4608 + 4096 + c4);
    } else if (b < 6400) {
        size_t j4 = (size_t)((b - 4352) * 256 + tid) * 4;
        float4 vk = *reinterpret_cast<const float4*>(Wk + j4);
        __half2* HK = reinterpret_cast<__half2*>(g_Wkh + j4);
        HK[0] = __floats2half2_rn(vk.x, vk.y);
        HK[1] = __floats2half2_rn(vk.z, vk.w);
        float4 vv = *reinterpret_cast<const float4*>(Wv + j4);
        __half2* H = reinterpret_cast<__half2*>(g_Wvh + j4);
        H[0] = __floats2half2_rn(vv.x, vv.y);
        H[1] = __floats2half2_rn(vv.z, vv.w);
    } else {
        // mask dtype normalization (reads only first 1024 bytes for detection)
        __shared__ int s_c0, s_chi;
        if (tid == 0) { s_c0 = 0; s_chi = 0; }
        __syncthreads();
        int c0 = 0, chi = 0;
        for (int t = tid; t < 256; t += 256) {
            unsigned char b0 = mask_raw[4*t], b1 = mask_raw[4*t+1],
                          b2 = mask_raw[4*t+2], b3 = mask_raw[4*t+3];
            if (b0) c0++;
            if (b1 | b2 | b3) chi++;
        }
        atomicAdd(&s_c0, c0); atomicAdd(&s_chi, chi);
        __syncthreads();
        int mode = (s_chi == 0) ? 1 : (s_c0 == 0 ? 2 : 0);
        for (int t = tid; t < 1024; t += 256) {
            int v;
            if (mode == 0) v = (mask_raw[t] != 0);
            else if (mode == 1) v = (((const int*)mask_raw)[t] != 0);
            else v = (((const float*)mask_raw)[t] != 0.0f);
            g_mask[t] = v;
        }
    }
}

// ---------------- launch ----------------
extern "C" void kernel_launch(void* const* d_in, const int* in_sizes, int n_in,
                              void* d_out, int out_size)
{
    const float* x = (const float*)d_in[0];
    const float* y = (const float*)d_in[1];
    const float* Wq = (const float*)d_in[2];
    const float* bq = (const float*)d_in[3];
    const float* Wk = (const float*)d_in[4];
    const float* bk = (const float*)d_in[5];
    const float* Wv = (const float*)d_in[6];
    const float* bv = (const float*)d_in[7];
    const float* Wp = (const float*)d_in[8];
    const float* gamma = (const float*)d_in[9];
    const unsigned char* mask_raw = (const unsigned char*)d_in[10];
    float* out = (float*)d_out;

    cudaFuncSetAttribute(gemm_proj,   cudaFuncAttributeMaxDynamicSharedMemorySize, SMTOT);
    cudaFuncSetAttribute(gemm_energy, cudaFuncAttributeMaxDynamicSharedMemorySize, SMTOT);
    cudaFuncSetAttribute(gemm_out,    cudaFuncAttributeMaxDynamicSharedMemorySize, SMTOT);

    // 1: prep(+mask), 2: proj, 3: energy(+block softmax), 4: rowfix (ncu #4), 5: out
    prep_all<<<6401, 256>>>(x, y, Wq, Wp, Wk, Wv, mask_raw);
    gemm_proj<<<dim3(36, 16, 3), 256, SMTOT>>>(bq, bk, bv);
    gemm_energy<<<dim3(8, 8, 16), 256, SMTOT>>>();
    rowfix_kernel<<<16384, 128>>>();
    gemm_out<<<dim3(8, 4, 16), 256, SMTOT>>>(gamma, out);
}

// round 17
// speedup vs baseline: 1.2712x; 1.2712x over previous
#include <cuda_runtime.h>
#include <cuda_fp16.h>
#include <cstdint>

#define NEG_INF -1e30f
typedef __half fp16;

// ---------------- scratch ----------------
__device__ __align__(256) fp16  g_xh[2048*512], g_xl[2048*512];
__device__ __align__(256) fp16  g_yh[2048*512], g_yl[2048*512];
__device__ __align__(256) fp16  g_Wqph[512*4608], g_Wqpl[512*4608];  // [Wq | Wp]
__device__ __align__(256) fp16  g_Wkh[512*4096];
__device__ __align__(256) fp16  g_Wvh[512*4096];
__device__ __align__(256) fp16  g_Qh[16*1024*512];                      // [h][2048][512] fp16
__device__ __align__(256) fp16  g_KTh[16*512*1024];                     // [hb][d][t]
__device__ __align__(256) fp16  g_V1T[16*512*1024];                     // [hb][d][s]
__device__ __align__(256) float g_E [(size_t)16*1024*1024];             // [hb][s][t] f32
__device__ __align__(256) fp16  g_AF[(size_t)16*1024*1024];             // [hb][s][t] fp16 attn
__device__ __align__(256) float g_XP[2048*512];
__device__ int g_mask[1024];

// ---------------- helpers ----------------
__device__ __forceinline__ uint32_t smem_u32(const void* p) {
    uint32_t a;
    asm("{ .reg .u64 t; cvta.to.shared.u64 t, %1; cvt.u32.u64 %0, t; }" : "=r"(a) : "l"(p));
    return a;
}
#define SWZA(x) ((x) ^ (((x) >> 3) & 0x70))
#define SWZB(x) ((x) ^ (((x) >> 4) & 0x70))
__device__ __forceinline__ void cp16(uint32_t dst, const void* src) {
    asm volatile("cp.async.cg.shared.global [%0], [%1], 16;" :: "r"(dst), "l"(src));
}
#define CP_COMMIT() asm volatile("cp.async.commit_group;" ::: "memory")
#define CP_WAIT1()  asm volatile("cp.async.wait_group 1;" ::: "memory")
__device__ __forceinline__ void ldm4(uint32_t* d, uint32_t a) {
    asm volatile("ldmatrix.sync.aligned.m8n8.x4.shared.b16 {%0,%1,%2,%3}, [%4];"
                 : "=r"(d[0]), "=r"(d[1]), "=r"(d[2]), "=r"(d[3]) : "r"(a));
}
__device__ __forceinline__ void ldm4t(uint32_t* d, uint32_t a) {
    asm volatile("ldmatrix.sync.aligned.m8n8.x4.trans.shared.b16 {%0,%1,%2,%3}, [%4];"
                 : "=r"(d[0]), "=r"(d[1]), "=r"(d[2]), "=r"(d[3]) : "r"(a));
}
__device__ __forceinline__ void mma16816(float* c, const uint32_t* a, uint32_t b0, uint32_t b1) {
    asm volatile("mma.sync.aligned.m16n8k16.row.col.f32.f16.f16.f32 "
                 "{%0,%1,%2,%3}, {%4,%5,%6,%7}, {%8,%9}, {%0,%1,%2,%3};"
                 : "+f"(c[0]), "+f"(c[1]), "+f"(c[2]), "+f"(c[3])
                 : "r"(a[0]), "r"(a[1]), "r"(a[2]), "r"(a[3]), "r"(b0), "r"(b1));
}
__device__ __forceinline__ void split2(float v, fp16& h, fp16& l) {
    h = __float2half(v);
    l = __float2half(v - __half2float(h));
}
__device__ __forceinline__ void split4_store(const float4 v, fp16* Hb, fp16* Lb, size_t off) {
    fp16 h0,l0,h1,l1,h2,l2,h3,l3;
    split2(v.x,h0,l0); split2(v.y,h1,l1); split2(v.z,h2,l2); split2(v.w,h3,l3);
    __half2* H = reinterpret_cast<__half2*>(Hb + off);
    __half2* L = reinterpret_cast<__half2*>(Lb + off);
    H[0] = __halves2half2(h0,h1); H[1] = __halves2half2(h2,h3);
    L[0] = __halves2half2(l0,l1); L[1] = __halves2half2(l2,l3);
}
__device__ __forceinline__ const fp16* pick(const fp16* p0, const fp16* p1, const fp16* p2, int s) {
    return s == 0 ? p0 : (s == 1 ? p1 : p2);
}

// ---------------- segmented GEMM core: CTA 128x128, 8 warps of 64x32, 3 stages ----
#define STG 32768
#define SMTOT (3*STG)

__device__ __forceinline__ void gemm_core(
    const fp16* A0, const fp16* A1, const fp16* A2,
    const fp16* B0, const fp16* B1, const fp16* B2,
    int KT, int ksh, int Kseg, int ldb, int m0, int n0,
    uint32_t sb, int tid, float c[4][4][4])
{
    const int wid = tid >> 5, lane = tid & 31;
    const int wm = (wid & 1) * 64, wn = (wid >> 1) * 32;

    uint32_t saoff[4], sboff[4];
#pragma unroll
    for (int i = 0; i < 4; i++) {
        int idx = tid + i * 256;
        saoff[i] = SWZA((idx >> 3) * 128 + (idx & 7) * 16);
        sboff[i] = 16384 + SWZB((idx >> 4) * 256 + (idx & 15) * 16);
    }
    const int aRow = tid >> 3, aCol = (tid & 7) * 8;
    const int bRow = tid >> 4, bCol = (tid & 15) * 8;
    const size_t aStep = (size_t)32 * Kseg;
    const size_t bStep = (size_t)16 * ldb;
    const size_t bAdv  = (size_t)64 * ldb;
    const int msk = (1 << ksh) - 1;

    const fp16* pA = A0;
    const fp16* pB = B0;
    int load_kt = 0;
    auto ldst = [&](int st) {
        if ((load_kt & msk) == 0) {
            int seg = load_kt >> ksh;
            pA = pick(A0, A1, A2, seg) + (size_t)(m0 + aRow) * Kseg + aCol;
            pB = pick(B0, B1, B2, seg) + (size_t)bRow * ldb + n0 + bCol;
        }
        uint32_t sa = sb + st * STG;
#pragma unroll
        for (int i = 0; i < 4; i++) cp16(sa + saoff[i], pA + i * aStep);
#pragma unroll
        for (int i = 0; i < 4; i++) cp16(sa + sboff[i], pB + i * bStep);
        pA += 64; pB += bAdv;
        load_kt++;
    };

    ldst(0); CP_COMMIT();
    ldst(1); CP_COMMIT();

    const int lo16 = lane & 15, hi2 = lane >> 4;
    uint32_t abase[4], bbase[2];
#pragma unroll
    for (int im = 0; im < 4; im++) abase[im] = (wm + im * 16 + lo16) * 128 + hi2 * 16;
#pragma unroll
    for (int in2 = 0; in2 < 2; in2++) bbase[in2] = lo16 * 256 + (wn + in2 * 16 + hi2 * 8) * 2;

    auto body = [&](int st) {
        const uint32_t sa = sb + st * STG, sbb = sa + 16384;
        uint32_t af[2][4][4], bfr[2][2][4];
#pragma unroll
        for (int im = 0; im < 4; im++) ldm4(af[0][im], sa + SWZA(abase[im]));
#pragma unroll
        for (int in2 = 0; in2 < 2; in2++) ldm4t(bfr[0][in2], sbb + SWZB(bbase[in2]));
#pragma unroll
        for (int kk = 0; kk < 4; kk++) {
            const int cur = kk & 1, nxt = cur ^ 1;
            if (kk < 3) {
#pragma unroll
                for (int im = 0; im < 4; im++) ldm4(af[nxt][im], sa + SWZA(abase[im] + (kk + 1) * 32));
#pragma unroll
                for (int in2 = 0; in2 < 2; in2++) ldm4t(bfr[nxt][in2], sbb + SWZB(bbase[in2] + (kk + 1) * 4096));
            }
#pragma unroll
            for (int im = 0; im < 4; im++)
#pragma unroll
                for (int in2 = 0; in2 < 2; in2++) {
                    mma16816(c[im][in2 * 2],     af[cur][im], bfr[cur][in2][0], bfr[cur][in2][1]);
                    mma16816(c[im][in2 * 2 + 1], af[cur][im], bfr[cur][in2][2], bfr[cur][in2][3]);
                }
        }
    };

    int st = 0;
    for (int kt = 0; kt < KT - 2; kt++) {
        CP_WAIT1();
        __syncthreads();
        int st2 = st + 2; if (st2 >= 3) st2 -= 3;
        ldst(st2);
        CP_COMMIT();
        body(st);
        st++; if (st == 3) st = 0;
    }
#pragma unroll
    for (int t2 = 0; t2 < 2; t2++) {
        CP_WAIT1();
        __syncthreads();
        CP_COMMIT();
        body(st);
        st++; if (st == 3) st = 0;
    }
    __syncthreads();
}

__device__ __forceinline__ void stage_acc(float* stf, int tid, float c[4][4][4]) {
    const int wid = tid >> 5, lane = tid & 31;
    const int wm = (wid & 1) * 64, wn = (wid >> 1) * 32;
    const int rin = lane >> 2, cp2 = (lane & 3) * 2;
#pragma unroll
    for (int im = 0; im < 4; im++)
#pragma unroll
        for (int i8 = 0; i8 < 4; i8++) {
            int rr = wm + im * 16 + rin, cc = wn + i8 * 8 + cp2;
            stf[rr * 129 + cc]           = c[im][i8][0];
            stf[rr * 129 + cc + 1]       = c[im][i8][1];
            stf[(rr + 8) * 129 + cc]     = c[im][i8][2];
            stf[(rr + 8) * 129 + cc + 1] = c[im][i8][3];
        }
    __syncthreads();
}

// ---------------- mega projection: z=0 Q (1-pass) + xp (3-pass), z=1 K(T) 2-pass, z=2 V(T) 1-pass ----
__global__ void __launch_bounds__(256, 2)
gemm_proj(const float* __restrict__ bq, const float* __restrict__ bk,
          const float* __restrict__ bv)
{
    extern __shared__ char smem[];
    const int z = blockIdx.z;
    const int xt = (z == 0) ? 36 : 32;
    if ((int)blockIdx.x >= xt) return;
    const uint32_t sb = smem_u32(smem);
    const int tid = threadIdx.x;
    const int m0 = blockIdx.y * 128, n0 = blockIdx.x * 128;

    float c[4][4][4];
#pragma unroll
    for (int i = 0; i < 4; i++)
#pragma unroll
        for (int j = 0; j < 4; j++)
#pragma unroll
            for (int q = 0; q < 4; q++) c[i][j][q] = 0.f;

    if (z == 0) {
        if (n0 < 4096)  // Q columns: 1-pass (Q is rounded to fp16 for 1-pass energy anyway)
            gemm_core(g_xh, nullptr, nullptr, g_Wqph, nullptr, nullptr, 8, 3, 512, 4608, m0, n0, sb, tid, c);
        else            // xp columns: full 3-pass (feeds output directly)
            gemm_core(g_xh, g_xh, g_xl, g_Wqph, g_Wqpl, g_Wqph, 24, 3, 512, 4608, m0, n0, sb, tid, c);
    } else if (z == 1)
        gemm_core(g_yh, g_yl, nullptr, g_Wkh, g_Wkh, nullptr, 16, 3, 512, 4096, m0, n0, sb, tid, c);
    else
        gemm_core(g_yh, nullptr, nullptr, g_Wvh, nullptr, nullptr, 8, 3, 512, 4096, m0, n0, sb, tid, c);

    float* stf = (float*)smem;
    stage_acc(stf, tid, c);

#pragma unroll 4
    for (int i = 0; i < 64; i++) {
        const int idx = tid + i * 256;
        int r, cc;
        if (z == 0) { r = idx >> 7; cc = idx & 127; } else { r = idx & 127; cc = idx >> 7; }
        float v = stf[r * 129 + cc];
        const int row2 = m0 + r, col = n0 + cc;
        if (z == 0) {
            if (col < 4096) {
                v += __ldg(bq + col);
                int h = col >> 9, d = col & 511;
                g_Qh[((size_t)h * 2048 + row2) * 512 + d] = __float2half(v);
            } else {
                g_XP[(size_t)row2 * 512 + (col - 4096)] = v;
            }
        } else if (z == 1) {
            v += __ldg(bk + col);
            int h = col >> 9, d = col & 511;
            int b = row2 >> 10, t = row2 & 1023;
            g_KTh[(size_t)(h * 2 + b) * 512 * 1024 + (size_t)d * 1024 + t] = __float2half(v);
        } else {
            v += __ldg(bv + col);
            int h = col >> 9, d = col & 511;
            int b = row2 >> 10, s = row2 & 1023;
            g_V1T[(size_t)(h * 2 + b) * 512 * 1024 + (size_t)d * 1024 + s] = __float2half(v);
        }
    }
}

// ---------------- energy: 1-pass (Qh·Kh), per hb, M=N=1024 ----------------
__global__ void __launch_bounds__(256, 2)
gemm_energy(void)
{
    extern __shared__ char smem[];
    const uint32_t sb = smem_u32(smem);
    const int tid = threadIdx.x, z = blockIdx.z;
    const int m0 = blockIdx.y * 128, n0 = blockIdx.x * 128;
    const fp16* Ah = g_Qh + (size_t)z * 1024 * 512;
    const fp16* Bh = g_KTh + (size_t)z * 512 * 1024;

    float c[4][4][4];
#pragma unroll
    for (int i = 0; i < 4; i++)
#pragma unroll
        for (int j = 0; j < 4; j++)
#pragma unroll
            for (int q = 0; q < 4; q++) c[i][j][q] = 0.f;

    gemm_core(Ah, nullptr, nullptr, Bh, nullptr, nullptr, 8, 3, 512, 1024, m0, n0, sb, tid, c);

    float* stf = (float*)smem;
    stage_acc(stf, tid, c);

#pragma unroll 4
    for (int i = 0; i < 64; i++) {
        const int idx = tid + i * 256;
        const int r = idx >> 7, cc = idx & 127;
        const int row2 = m0 + r, col = n0 + cc;
        float v = stf[r * 129 + cc];
        g_E[(size_t)z * 1048576 + (size_t)row2 * 1024 + col] = g_mask[col] ? v : NEG_INF;
    }
}

// ---------------- out ----------------
__global__ void __launch_bounds__(256, 2)
gemm_out(const float* __restrict__ gamma, float* __restrict__ out)
{
    extern __shared__ char smem[];
    const uint32_t sb = smem_u32(smem);
    const int tid = threadIdx.x, z = blockIdx.z;
    const int m0 = blockIdx.y * 128, n0 = blockIdx.x * 128;
    const fp16* A0 = g_V1T + (size_t)z * 512 * 1024;
    const fp16* B0 = g_AF + (size_t)z * 1024 * 1024;

    float c[4][4][4];
#pragma unroll
    for (int i = 0; i < 4; i++)
#pragma unroll
        for (int j = 0; j < 4; j++)
#pragma unroll
            for (int q = 0; q < 4; q++) c[i][j][q] = 0.f;

    gemm_core(A0, nullptr, nullptr, B0, nullptr, nullptr, 16, 4, 1024, 1024, m0, n0, sb, tid, c);

    float* stf = (float*)smem;
    stage_acc(stf, tid, c);

    const int h = z >> 1, b = z & 1;
    const float g = __ldg(gamma + h);
    const float inv = 1.0f / (g + 1.0f);
#pragma unroll 4
    for (int i = 0; i < 64; i++) {
        const int idx = tid + i * 256;
        const int r = idx & 127, cc = idx >> 7;
        const int d = m0 + r, t = n0 + cc;
        float v = stf[r * 129 + cc];
        float xp = __ldg(g_XP + ((size_t)b * 1024 + t) * 512 + d);
        out[(((size_t)(b * 8 + h)) * 1024 + t) * 512 + d] = (g * v + xp) * inv;
    }
}

// ---------------- merged prep (incl. mask normalization at block 6400) ----------------
__global__ void prep_all(const float* __restrict__ x, const float* __restrict__ y,
                         const float* __restrict__ Wq, const float* __restrict__ Wp,
                         const float* __restrict__ Wk, const float* __restrict__ Wv,
                         const unsigned char* __restrict__ mask_raw)
{
    const int b = blockIdx.x, tid = threadIdx.x;
    if (b < 2048) {
        int i = b * 256 + tid;
        int sel = i >= 262144;
        size_t j4 = (size_t)(i & 262143) * 4;
        float4 v = *reinterpret_cast<const float4*>((sel ? y : x) + j4);
        if (sel) split4_store(v, g_yh, g_yl, j4);
        else     split4_store(v, g_xh, g_xl, j4);
    } else if (b < 4096) {
        int i = (b - 2048) * 256 + tid;
        int r = i >> 10;
        size_t c4 = (size_t)(i & 1023) * 4;
        float4 v = *reinterpret_cast<const float4*>(Wq + (size_t)r * 4096 + c4);
        split4_store(v, g_Wqph, g_Wqpl, (size_t)r * 4608 + c4);
    } else if (b < 4352) {
        int i = (b - 4096) * 256 + tid;
        int r = i >> 7;
        size_t c4 = (size_t)(i & 127) * 4;
        float4 v = *reinterpret_cast<const float4*>(Wp + (size_t)r * 512 + c4);
        split4_store(v, g_Wqph, g_Wqpl, (size_t)r * 4608 + 4096 + c4);
    } else if (b < 6400) {
        size_t j4 = (size_t)((b - 4352) * 256 + tid) * 4;
        float4 vk = *reinterpret_cast<const float4*>(Wk + j4);
        __half2* HK = reinterpret_cast<__half2*>(g_Wkh + j4);
        HK[0] = __floats2half2_rn(vk.x, vk.y);
        HK[1] = __floats2half2_rn(vk.z, vk.w);
        float4 vv = *reinterpret_cast<const float4*>(Wv + j4);
        __half2* H = reinterpret_cast<__half2*>(g_Wvh + j4);
        H[0] = __floats2half2_rn(vv.x, vv.y);
        H[1] = __floats2half2_rn(vv.z, vv.w);
    } else {
        __shared__ int s_c0, s_chi;
        if (tid == 0) { s_c0 = 0; s_chi = 0; }
        __syncthreads();
        int c0 = 0, chi = 0;
        for (int t = tid; t < 256; t += 256) {
            unsigned char b0 = mask_raw[4*t], b1 = mask_raw[4*t+1],
                          b2 = mask_raw[4*t+2], b3 = mask_raw[4*t+3];
            if (b0) c0++;
            if (b1 | b2 | b3) chi++;
        }
        atomicAdd(&s_c0, c0); atomicAdd(&s_chi, chi);
        __syncthreads();
        int mode = (s_chi == 0) ? 1 : (s_c0 == 0 ? 2 : 0);
        for (int t = tid; t < 1024; t += 256) {
            int v;
            if (mode == 0) v = (mask_raw[t] != 0);
            else if (mode == 1) v = (((const int*)mask_raw)[t] != 0);
            else v = (((const float*)mask_raw)[t] != 0.0f);
            g_mask[t] = v;
        }
    }
}

// warp-per-row softmax: block = 8 warps = 8 rows; reads fp32 g_E, writes fp16 g_AF
__global__ void softmax_kernel(void) {
    const int w = threadIdx.x >> 5, lane = threadIdx.x & 31;
    const size_t row = (size_t)blockIdx.x * 8 + w;
    const float4* p = reinterpret_cast<const float4*>(g_E + row * 1024);
    float4 v[8];
#pragma unroll
    for (int j = 0; j < 8; j++) v[j] = p[lane + 32 * j];
    float mx = -1e38f;
#pragma unroll
    for (int j = 0; j < 8; j++)
        mx = fmaxf(mx, fmaxf(fmaxf(v[j].x, v[j].y), fmaxf(v[j].z, v[j].w)));
#pragma unroll
    for (int o = 16; o > 0; o >>= 1) mx = fmaxf(mx, __shfl_xor_sync(~0u, mx, o));
    float s = 0.f;
#pragma unroll
    for (int j = 0; j < 8; j++) {
        v[j].x = __expf(v[j].x - mx); v[j].y = __expf(v[j].y - mx);
        v[j].z = __expf(v[j].z - mx); v[j].w = __expf(v[j].w - mx);
        s += v[j].x + v[j].y + v[j].z + v[j].w;
    }
#pragma unroll
    for (int o = 16; o > 0; o >>= 1) s += __shfl_xor_sync(~0u, s, o);
    const float inv = 1.0f / s;
    __half2* q = reinterpret_cast<__half2*>(g_AF + row * 1024);
#pragma unroll
    for (int j = 0; j < 8; j++) {
        q[2 * (lane + 32 * j)]     = __floats2half2_rn(v[j].x * inv, v[j].y * inv);
        q[2 * (lane + 32 * j) + 1] = __floats2half2_rn(v[j].z * inv, v[j].w * inv);
    }
}

// ---------------- launch ----------------
extern "C" void kernel_launch(void* const* d_in, const int* in_sizes, int n_in,
                              void* d_out, int out_size)
{
    const float* x = (const float*)d_in[0];
    const float* y = (const float*)d_in[1];
    const float* Wq = (const float*)d_in[2];
    const float* bq = (const float*)d_in[3];
    const float* Wk = (const float*)d_in[4];
    const float* bk = (const float*)d_in[5];
    const float* Wv = (const float*)d_in[6];
    const float* bv = (const float*)d_in[7];
    const float* Wp = (const float*)d_in[8];
    const float* gamma = (const float*)d_in[9];
    const unsigned char* mask_raw = (const unsigned char*)d_in[10];
    float* out = (float*)d_out;

    cudaFuncSetAttribute(gemm_proj,   cudaFuncAttributeMaxDynamicSharedMemorySize, SMTOT);
    cudaFuncSetAttribute(gemm_energy, cudaFuncAttributeMaxDynamicSharedMemorySize, SMTOT);
    cudaFuncSetAttribute(gemm_out,    cudaFuncAttributeMaxDynamicSharedMemorySize, SMTOT);

    // 1: prep(+mask), 2: proj, 3: energy, 4: softmax (ncu #4), 5: out
    prep_all<<<6401, 256>>>(x, y, Wq, Wp, Wk, Wv, mask_raw);
    gemm_proj<<<dim3(36, 16, 3), 256, SMTOT>>>(bq, bk, bv);
    gemm_energy<<<dim3(8, 8, 16), 256, SMTOT>>>();
    softmax_kernel<<<2048, 256>>>();
    gemm_out<<<dim3(8, 4, 16), 256, SMTOT>>>(gamma, out);
}